// round 2
// baseline (speedup 1.0000x reference)
#include <cuda_runtime.h>

#define TPB 256
#define CHUNK 6
#define M_SAMPLES 1535
#define RGB_OFF 0
#define ALPHA_OFF 384
#define DEPTH_OFF (384 + 128 * 1535)

// Per-ray SH-contracted atom table: [ray][f][a] float4 (rgb_raw contractions + sigma channel)
__device__ float4 g_R[128 * 512 * 16];

__device__ __forceinline__ float dot9(const float* s, const float* a) {
    float v = s[0] * a[0];
#pragma unroll
    for (int k = 1; k < 9; k++) v = fmaf(s[k], a[k], v);
    return v;
}

// Kernel A: R[r,f,a,c] = sum_k shm[r,k] * atoms[f,a,9c+k];  R[...,3] = atoms[f,a,27]
__global__ void precompute_R(const float* __restrict__ rays_d,
                             const float* __restrict__ atoms) {
    __shared__ float s_at[448];        // atoms[f] row: 16 atoms x 28
    __shared__ float s_shm[128][9];
    int f = blockIdx.x;
    int tid = threadIdx.x;
    for (int i = tid; i < 448; i += TPB) s_at[i] = atoms[f * 448 + i];
    if (tid < 128) {
        float x = rays_d[tid * 3 + 0];
        float y = rays_d[tid * 3 + 1];
        float z = rays_d[tid * 3 + 2];
        const float C0 = 0.28209479177387814f;
        const float C1 = 0.4886025119029199f;
        s_shm[tid][0] = C0;
        s_shm[tid][1] = -C1 * y;
        s_shm[tid][2] = C1 * z;
        s_shm[tid][3] = -C1 * x;
        s_shm[tid][4] = 1.0925484305920792f * x * y;
        s_shm[tid][5] = -1.0925484305920792f * y * z;
        s_shm[tid][6] = 0.31539156525252005f * (2.0f * z * z - x * x - y * y);
        s_shm[tid][7] = -1.0925484305920792f * x * z;
        s_shm[tid][8] = 0.5462742152960396f * (x * x - y * y);
    }
    __syncthreads();
    for (int p = tid; p < 2048; p += TPB) {
        int a = p & 15;
        int r = p >> 4;
        const float* ar = s_at + a * 28;
        const float* sm = s_shm[r];
        float4 o;
        o.x = dot9(sm, ar);
        o.y = dot9(sm, ar + 9);
        o.z = dot9(sm, ar + 18);
        o.w = ar[27];
        g_R[((size_t)r * 512 + f) * 16 + a] = o;
    }
}

// Kernel B: one block per ray.
__global__ void __launch_bounds__(TPB, 1)
render(const float* __restrict__ rays_o, const float* __restrict__ rays_d,
       const float* __restrict__ grid, float* __restrict__ out) {
    extern __shared__ float4 sm4[];
    float4* Rs      = sm4;                          // 16 * 513 float4 (padded stride)
    float* alpha_s  = (float*)(sm4 + 16 * 513);     // 1536
    float* sr       = alpha_s + 1536;
    float* sg       = sr + 1536;
    float* sb       = sg + 1536;
    float* scan_s   = sb + 1536;                    // 256
    float* red      = scan_s + 256;                 // 40

    const int ray = blockIdx.x;
    const int tid = threadIdx.x;

    // Load this ray's R slice into padded SMEM layout [a][f]
    const float4* Rg = g_R + (size_t)ray * 8192;
#pragma unroll 4
    for (int i = tid; i < 8192; i += TPB) {
        int f = i >> 4;
        int a = i & 15;
        Rs[a * 513 + f] = Rg[i];
    }

    const float R = 1.3f;
    float ox = rays_o[ray * 3 + 0], oy = rays_o[ray * 3 + 1], oz = rays_o[ray * 3 + 2];
    float dx = rays_d[ray * 3 + 0], dy = rays_d[ray * 3 + 1], dz = rays_d[ray * 3 + 2];

    float mnx = fminf(__fdiv_rn(__fsub_rn(R, ox), dx), __fdiv_rn(__fsub_rn(-R, ox), dx));
    float mny = fminf(__fdiv_rn(__fsub_rn(R, oy), dy), __fdiv_rn(__fsub_rn(-R, oy), dy));
    float mnz = fminf(__fdiv_rn(__fsub_rn(R, oz), dz), __fdiv_rn(__fsub_rn(-R, oz), dz));
    float start = fmaxf(fmaxf(mnx, mny), mnz);
    float normd = __fsqrt_rn(__fadd_rn(__fadd_rn(__fmul_rn(dx, dx), __fmul_rn(dy, dy)), __fmul_rn(dz, dz)));

    const float STEPF = (float)(2.6 / 512.0);
    const float LIM = (float)(1.0 - 1e-6);

    __syncthreads();

    const int m0 = tid * CHUNK;
#pragma unroll 1
    for (int j = 0; j < CHUNK; j++) {
        int m = m0 + j;
        if (m < M_SAMPLES) {
            float t  = __fadd_rn(start, __fmul_rn((float)m, STEPF));
            float px = __fadd_rn(ox, __fmul_rn(t, dx));
            float py = __fadd_rn(oy, __fmul_rn(t, dy));
            float pz = __fadd_rn(oz, __fmul_rn(t, dz));
            bool mask = (px > -R) && (px < R) && (py > -R) && (py < R) && (pz > -R) && (pz < R);

            float nx = fminf(fmaxf(__fdiv_rn(__fadd_rn(px, R), 2.6f), 0.0f), LIM);
            float ny = fminf(fmaxf(__fdiv_rn(__fadd_rn(py, R), 2.6f), 0.0f), LIM);
            float nz = fminf(fmaxf(__fdiv_rn(__fadd_rn(pz, R), 2.6f), 0.0f), LIM);

            float cpx = __fmul_rn(nx, 32.0f);
            float cpy = __fmul_rn(ny, 32.0f);
            float cpz = __fmul_rn(nz, 32.0f);
            float cfx = fminf(fmaxf(floorf(cpx), 0.0f), 31.0f);
            float cfy = fminf(fmaxf(floorf(cpy), 0.0f), 31.0f);
            float cfz = fminf(fmaxf(floorf(cpz), 0.0f), 31.0f);
            int cell = (((int)cfx) * 32 + (int)cfy) * 32 + (int)cfz;

            const float4* g4 = (const float4*)grid + cell * 4;
            float4 q0 = __ldg(g4 + 0), q1 = __ldg(g4 + 1), q2 = __ldg(g4 + 2), q3 = __ldg(g4 + 3);
            float cf[16] = {q0.x, q0.y, q0.z, q0.w, q1.x, q1.y, q1.z, q1.w,
                            q2.x, q2.y, q2.z, q2.w, q3.x, q3.y, q3.z, q3.w};

            float fpx = __fsub_rn(__fmul_rn(__fsub_rn(cpx, cfx), 8.0f), 0.5f);
            float fpy = __fsub_rn(__fmul_rn(__fsub_rn(cpy, cfy), 8.0f), 0.5f);
            float fpz = __fsub_rn(__fmul_rn(__fsub_rn(cpz, cfz), 8.0f), 0.5f);
            float f0x = floorf(fpx), f0y = floorf(fpy), f0z = floorf(fpz);
            float wx = __fsub_rn(fpx, f0x);
            float wy = __fsub_rn(fpy, f0y);
            float wz = __fsub_rn(fpz, f0z);
            int i0x = (int)f0x, i0y = (int)f0y, i0z = (int)f0z;

            float4 acc = make_float4(0.f, 0.f, 0.f, 0.f);
#pragma unroll
            for (int c = 0; c < 8; c++) {
                int ddx = c >> 2, ddy = (c >> 1) & 1, ddz = c & 1;
                int ix = min(max(i0x + ddx, 0), 7);
                int iy = min(max(i0y + ddy, 0), 7);
                int iz = min(max(i0z + ddz, 0), 7);
                float wt = __fmul_rn(__fmul_rn(ddx ? wx : __fsub_rn(1.0f, wx),
                                               ddy ? wy : __fsub_rn(1.0f, wy)),
                                     ddz ? wz : __fsub_rn(1.0f, wz));
                int f = (ix * 8 + iy) * 8 + iz;
                const float4* rp = Rs + f;
                float4 v = make_float4(0.f, 0.f, 0.f, 0.f);
#pragma unroll
                for (int a = 0; a < 16; a++) {
                    float4 r = rp[a * 513];
                    v.x = fmaf(cf[a], r.x, v.x);
                    v.y = fmaf(cf[a], r.y, v.y);
                    v.z = fmaf(cf[a], r.z, v.z);
                    v.w = fmaf(cf[a], r.w, v.w);
                }
                acc.x = fmaf(wt, v.x, acc.x);
                acc.y = fmaf(wt, v.y, acc.y);
                acc.z = fmaf(wt, v.z, acc.z);
                acc.w = fmaf(wt, v.w, acc.w);
            }

            float sigma = mask ? fmaxf(acc.w, 0.0f) : 0.0f;
            float t1 = __fadd_rn(start, __fmul_rn((float)(m + 1), STEPF));
            float dist = __fmul_rn(__fsub_rn(t1, t), normd);
            // alpha = 1 - exp(-sigma*dist): x is tiny, so alpha inherits the
            // ABSOLUTE error of exp near 1.0 (catastrophic cancellation).
            // Use fp64 exp -> correctly-rounded f32, then subtract in f32 to
            // mirror the reference's rounding sequence. CUDA expf (MUFU.EX2,
            // ~4 ulp abs near 1.0) caused the 1.8e-2 alpha error in R1.
            float x_al = __fmul_rn(sigma, dist);
            float ex = (float)exp(-(double)x_al);
            float al = __fsub_rn(1.0f, ex);
            alpha_s[m] = al;
            out[ALPHA_OFF + ray * M_SAMPLES + m] = al;

            float rx = mask ? acc.x : 0.0f;
            float ry = mask ? acc.y : 0.0f;
            float rz = mask ? acc.z : 0.0f;
            sr[m] = __fdiv_rn(1.0f, __fadd_rn(1.0f, expf(-rx)));
            sg[m] = __fdiv_rn(1.0f, __fadd_rn(1.0f, expf(-ry)));
            sb[m] = __fdiv_rn(1.0f, __fadd_rn(1.0f, expf(-rz)));
        }
    }
    __syncthreads();

    // per-thread chunk product of (1 - alpha + 1e-10)
    float p = 1.0f;
#pragma unroll
    for (int j = 0; j < CHUNK; j++) {
        int m = m0 + j;
        if (m < M_SAMPLES)
            p = __fmul_rn(p, __fadd_rn(__fsub_rn(1.0f, alpha_s[m]), 1e-10f));
    }
    scan_s[tid] = p;
    __syncthreads();
    // inclusive Hillis-Steele scan over 256 threads
#pragma unroll
    for (int off = 1; off < TPB; off <<= 1) {
        float v = scan_s[tid];
        float u = (tid >= off) ? scan_s[tid - off] : 1.0f;
        __syncthreads();
        scan_s[tid] = u * v;
        __syncthreads();
    }
    float trans = (tid == 0) ? 1.0f : scan_s[tid - 1];

    float ar = 0.f, ag = 0.f, abv = 0.f, dep = 0.f, sal = 0.f;
#pragma unroll
    for (int j = 0; j < CHUNK; j++) {
        int m = m0 + j;
        if (m < M_SAMPLES) {
            float a = alpha_s[m];
            float abl = __fmul_rn(a, trans);
            ar = fmaf(abl, sr[m], ar);
            ag = fmaf(abl, sg[m], ag);
            abv = fmaf(abl, sb[m], abv);
            float t = __fadd_rn(start, __fmul_rn((float)m, STEPF));
            dep = fmaf(abl, t, dep);
            sal = __fadd_rn(sal, abl);
            trans = __fmul_rn(trans, __fadd_rn(__fsub_rn(1.0f, a), 1e-10f));
        }
    }

    // block reduction of 5 scalars
    const unsigned full = 0xffffffffu;
#pragma unroll
    for (int off = 16; off; off >>= 1) {
        ar  += __shfl_down_sync(full, ar, off);
        ag  += __shfl_down_sync(full, ag, off);
        abv += __shfl_down_sync(full, abv, off);
        dep += __shfl_down_sync(full, dep, off);
        sal += __shfl_down_sync(full, sal, off);
    }
    int w = tid >> 5, lane = tid & 31;
    if (lane == 0) {
        red[w] = ar; red[8 + w] = ag; red[16 + w] = abv; red[24 + w] = dep; red[32 + w] = sal;
    }
    __syncthreads();
    if (tid == 0) {
        float R0 = 0.f, R1 = 0.f, R2 = 0.f, D = 0.f, S = 0.f;
#pragma unroll
        for (int i = 0; i < 8; i++) {
            R0 += red[i]; R1 += red[8 + i]; R2 += red[16 + i]; D += red[24 + i]; S += red[32 + i];
        }
        float bg = __fsub_rn(1.0f, S);
        out[RGB_OFF + ray * 3 + 0] = R0 + bg;
        out[RGB_OFF + ray * 3 + 1] = R1 + bg;
        out[RGB_OFF + ray * 3 + 2] = R2 + bg;
        out[DEPTH_OFF + ray] = D;
    }
}

extern "C" void kernel_launch(void* const* d_in, const int* in_sizes, int n_in,
                              void* d_out, int out_size) {
    const float* rays_o = (const float*)d_in[0];
    const float* rays_d = (const float*)d_in[1];
    const float* grid   = (const float*)d_in[2];
    const float* atoms  = (const float*)d_in[3];
    float* out = (float*)d_out;

    // SMEM: R table (16*513 float4) + alpha(1536) + 3x srgb(1536) + scan(256) + red(40)
    const int smem_bytes = 16 * 513 * 16 + (1536 * 4 + 256 + 40) * 4;
    cudaFuncSetAttribute(render, cudaFuncAttributeMaxDynamicSharedMemorySize, smem_bytes);

    precompute_R<<<512, TPB>>>(rays_d, atoms);
    render<<<128, TPB, smem_bytes>>>(rays_o, rays_d, grid, out);
}

// round 3
// speedup vs baseline: 1.8289x; 1.8289x over previous
#include <cuda_runtime.h>

#define TPB 512
#define CHUNK 3
#define M_SAMPLES 1535
#define RGB_OFF 0
#define ALPHA_OFF 384
#define DEPTH_OFF (384 + 128 * 1535)

// Per-ray SH-contracted atom table: [ray][f][a] float4 (rgb_raw contractions + sigma channel)
__device__ float4 g_R[128 * 512 * 16];

__device__ __forceinline__ float dot9(const float* s, const float* a) {
    float v = s[0] * a[0];
#pragma unroll
    for (int k = 1; k < 9; k++) v = fmaf(s[k], a[k], v);
    return v;
}

// Kernel A: R[r,f,a,c] = sum_k shm[r,k] * atoms[f,a,9c+k];  R[...,3] = atoms[f,a,27]
__global__ void precompute_R(const float* __restrict__ rays_d,
                             const float* __restrict__ atoms) {
    __shared__ float s_at[448];        // atoms[f] row: 16 atoms x 28
    __shared__ float s_shm[128][9];
    int f = blockIdx.x;
    int tid = threadIdx.x;
    for (int i = tid; i < 448; i += 256) s_at[i] = atoms[f * 448 + i];
    if (tid < 128) {
        float x = rays_d[tid * 3 + 0];
        float y = rays_d[tid * 3 + 1];
        float z = rays_d[tid * 3 + 2];
        const float C0 = 0.28209479177387814f;
        const float C1 = 0.4886025119029199f;
        s_shm[tid][0] = C0;
        s_shm[tid][1] = -C1 * y;
        s_shm[tid][2] = C1 * z;
        s_shm[tid][3] = -C1 * x;
        s_shm[tid][4] = 1.0925484305920792f * x * y;
        s_shm[tid][5] = -1.0925484305920792f * y * z;
        s_shm[tid][6] = 0.31539156525252005f * (2.0f * z * z - x * x - y * y);
        s_shm[tid][7] = -1.0925484305920792f * x * z;
        s_shm[tid][8] = 0.5462742152960396f * (x * x - y * y);
    }
    __syncthreads();
    for (int p = tid; p < 2048; p += 256) {
        int a = p & 15;
        int r = p >> 4;
        const float* ar = s_at + a * 28;
        const float* sm = s_shm[r];
        float4 o;
        o.x = dot9(sm, ar);
        o.y = dot9(sm, ar + 9);
        o.z = dot9(sm, ar + 18);
        o.w = ar[27];
        g_R[((size_t)r * 512 + f) * 16 + a] = o;
    }
}

// Kernel B: one block per ray.
__global__ void __launch_bounds__(TPB, 1)
render(const float* __restrict__ rays_o, const float* __restrict__ rays_d,
       const float* __restrict__ grid, float* __restrict__ out) {
    extern __shared__ float4 sm4[];
    float4* Rs      = sm4;                          // 16 * 513 float4 (padded stride)
    float* alpha_s  = (float*)(sm4 + 16 * 513);     // 1536
    float* sr       = alpha_s + 1536;
    float* sg       = sr + 1536;
    float* sb       = sg + 1536;
    float* scan_s   = sb + 1536;                    // 512
    float* red      = scan_s + TPB;                 // 80

    const int ray = blockIdx.x;
    const int tid = threadIdx.x;

    // Load this ray's R slice into padded SMEM layout [a][f]
    const float4* Rg = g_R + (size_t)ray * 8192;
#pragma unroll 4
    for (int i = tid; i < 8192; i += TPB) {
        int f = i >> 4;
        int a = i & 15;
        Rs[a * 513 + f] = Rg[i];
    }

    const float R = 1.3f;
    float ox = rays_o[ray * 3 + 0], oy = rays_o[ray * 3 + 1], oz = rays_o[ray * 3 + 2];
    float dx = rays_d[ray * 3 + 0], dy = rays_d[ray * 3 + 1], dz = rays_d[ray * 3 + 2];

    float mnx = fminf(__fdiv_rn(__fsub_rn(R, ox), dx), __fdiv_rn(__fsub_rn(-R, ox), dx));
    float mny = fminf(__fdiv_rn(__fsub_rn(R, oy), dy), __fdiv_rn(__fsub_rn(-R, oy), dy));
    float mnz = fminf(__fdiv_rn(__fsub_rn(R, oz), dz), __fdiv_rn(__fsub_rn(-R, oz), dz));
    float start = fmaxf(fmaxf(mnx, mny), mnz);
    float normd = __fsqrt_rn(__fadd_rn(__fadd_rn(__fmul_rn(dx, dx), __fmul_rn(dy, dy)), __fmul_rn(dz, dz)));

    const float STEPF = (float)(2.6 / 512.0);
    const float LIM = (float)(1.0 - 1e-6);

    __syncthreads();

    // Phase 1: adjacent lanes process adjacent samples (m = tid + j*TPB) ->
    // corner f indices nearly identical across a warp -> LDS broadcast, and
    // the alpha global store is coalesced.
#pragma unroll 1
    for (int j = 0; j < CHUNK; j++) {
        int m = tid + j * TPB;
        if (m < M_SAMPLES) {
            float t  = __fadd_rn(start, __fmul_rn((float)m, STEPF));
            float px = __fadd_rn(ox, __fmul_rn(t, dx));
            float py = __fadd_rn(oy, __fmul_rn(t, dy));
            float pz = __fadd_rn(oz, __fmul_rn(t, dz));
            bool mask = (px > -R) && (px < R) && (py > -R) && (py < R) && (pz > -R) && (pz < R);

            float nx = fminf(fmaxf(__fdiv_rn(__fadd_rn(px, R), 2.6f), 0.0f), LIM);
            float ny = fminf(fmaxf(__fdiv_rn(__fadd_rn(py, R), 2.6f), 0.0f), LIM);
            float nz = fminf(fmaxf(__fdiv_rn(__fadd_rn(pz, R), 2.6f), 0.0f), LIM);

            float cpx = __fmul_rn(nx, 32.0f);
            float cpy = __fmul_rn(ny, 32.0f);
            float cpz = __fmul_rn(nz, 32.0f);
            float cfx = fminf(fmaxf(floorf(cpx), 0.0f), 31.0f);
            float cfy = fminf(fmaxf(floorf(cpy), 0.0f), 31.0f);
            float cfz = fminf(fmaxf(floorf(cpz), 0.0f), 31.0f);
            int cell = (((int)cfx) * 32 + (int)cfy) * 32 + (int)cfz;

            const float4* g4 = (const float4*)grid + cell * 4;
            float4 q0 = __ldg(g4 + 0), q1 = __ldg(g4 + 1), q2 = __ldg(g4 + 2), q3 = __ldg(g4 + 3);
            float cf[16] = {q0.x, q0.y, q0.z, q0.w, q1.x, q1.y, q1.z, q1.w,
                            q2.x, q2.y, q2.z, q2.w, q3.x, q3.y, q3.z, q3.w};

            float fpx = __fsub_rn(__fmul_rn(__fsub_rn(cpx, cfx), 8.0f), 0.5f);
            float fpy = __fsub_rn(__fmul_rn(__fsub_rn(cpy, cfy), 8.0f), 0.5f);
            float fpz = __fsub_rn(__fmul_rn(__fsub_rn(cpz, cfz), 8.0f), 0.5f);
            float f0x = floorf(fpx), f0y = floorf(fpy), f0z = floorf(fpz);
            float wx = __fsub_rn(fpx, f0x);
            float wy = __fsub_rn(fpy, f0y);
            float wz = __fsub_rn(fpz, f0z);
            int i0x = (int)f0x, i0y = (int)f0y, i0z = (int)f0z;

            float4 acc = make_float4(0.f, 0.f, 0.f, 0.f);
#pragma unroll
            for (int c = 0; c < 8; c++) {
                int ddx = c >> 2, ddy = (c >> 1) & 1, ddz = c & 1;
                int ix = min(max(i0x + ddx, 0), 7);
                int iy = min(max(i0y + ddy, 0), 7);
                int iz = min(max(i0z + ddz, 0), 7);
                float wt = __fmul_rn(__fmul_rn(ddx ? wx : __fsub_rn(1.0f, wx),
                                               ddy ? wy : __fsub_rn(1.0f, wy)),
                                     ddz ? wz : __fsub_rn(1.0f, wz));
                int f = (ix * 8 + iy) * 8 + iz;
                const float4* rp = Rs + f;
                float4 v = make_float4(0.f, 0.f, 0.f, 0.f);
#pragma unroll
                for (int a = 0; a < 16; a++) {
                    float4 r = rp[a * 513];
                    v.x = fmaf(cf[a], r.x, v.x);
                    v.y = fmaf(cf[a], r.y, v.y);
                    v.z = fmaf(cf[a], r.z, v.z);
                    v.w = fmaf(cf[a], r.w, v.w);
                }
                acc.x = fmaf(wt, v.x, acc.x);
                acc.y = fmaf(wt, v.y, acc.y);
                acc.z = fmaf(wt, v.z, acc.z);
                acc.w = fmaf(wt, v.w, acc.w);
            }

            float sigma = mask ? fmaxf(acc.w, 0.0f) : 0.0f;
            float t1 = __fadd_rn(start, __fmul_rn((float)(m + 1), STEPF));
            float dist = __fmul_rn(__fsub_rn(t1, t), normd);
            // alpha = 1 - exp(-x), x tiny: needs correctly-rounded exp near 1.0
            // (fp64 path) to match the reference's cancellation behavior.
            float x_al = __fmul_rn(sigma, dist);
            float ex = (float)exp(-(double)x_al);
            float al = __fsub_rn(1.0f, ex);
            alpha_s[m] = al;
            out[ALPHA_OFF + ray * M_SAMPLES + m] = al;

            float rx = mask ? acc.x : 0.0f;
            float ry = mask ? acc.y : 0.0f;
            float rz = mask ? acc.z : 0.0f;
            sr[m] = __fdiv_rn(1.0f, __fadd_rn(1.0f, expf(-rx)));
            sg[m] = __fdiv_rn(1.0f, __fadd_rn(1.0f, expf(-ry)));
            sb[m] = __fdiv_rn(1.0f, __fadd_rn(1.0f, expf(-rz)));
        }
    }
    __syncthreads();

    // Phase 2: contiguous chunks per thread (m = tid*CHUNK + j) for the scan.
    const int m0 = tid * CHUNK;
    float p = 1.0f;
#pragma unroll
    for (int j = 0; j < CHUNK; j++) {
        int m = m0 + j;
        if (m < M_SAMPLES)
            p = __fmul_rn(p, __fadd_rn(__fsub_rn(1.0f, alpha_s[m]), 1e-10f));
    }
    scan_s[tid] = p;
    __syncthreads();
    // inclusive Hillis-Steele scan over TPB threads
#pragma unroll
    for (int off = 1; off < TPB; off <<= 1) {
        float v = scan_s[tid];
        float u = (tid >= off) ? scan_s[tid - off] : 1.0f;
        __syncthreads();
        scan_s[tid] = u * v;
        __syncthreads();
    }
    float trans = (tid == 0) ? 1.0f : scan_s[tid - 1];

    float ar = 0.f, ag = 0.f, abv = 0.f, dep = 0.f, sal = 0.f;
#pragma unroll
    for (int j = 0; j < CHUNK; j++) {
        int m = m0 + j;
        if (m < M_SAMPLES) {
            float a = alpha_s[m];
            float abl = __fmul_rn(a, trans);
            ar = fmaf(abl, sr[m], ar);
            ag = fmaf(abl, sg[m], ag);
            abv = fmaf(abl, sb[m], abv);
            float t = __fadd_rn(start, __fmul_rn((float)m, STEPF));
            dep = fmaf(abl, t, dep);
            sal = __fadd_rn(sal, abl);
            trans = __fmul_rn(trans, __fadd_rn(__fsub_rn(1.0f, a), 1e-10f));
        }
    }

    // block reduction of 5 scalars
    const unsigned full = 0xffffffffu;
#pragma unroll
    for (int off = 16; off; off >>= 1) {
        ar  += __shfl_down_sync(full, ar, off);
        ag  += __shfl_down_sync(full, ag, off);
        abv += __shfl_down_sync(full, abv, off);
        dep += __shfl_down_sync(full, dep, off);
        sal += __shfl_down_sync(full, sal, off);
    }
    int w = tid >> 5, lane = tid & 31;
    const int NW = TPB / 32;
    if (lane == 0) {
        red[w] = ar; red[NW + w] = ag; red[2 * NW + w] = abv;
        red[3 * NW + w] = dep; red[4 * NW + w] = sal;
    }
    __syncthreads();
    if (tid == 0) {
        float R0 = 0.f, R1 = 0.f, R2 = 0.f, D = 0.f, S = 0.f;
#pragma unroll
        for (int i = 0; i < NW; i++) {
            R0 += red[i]; R1 += red[NW + i]; R2 += red[2 * NW + i];
            D += red[3 * NW + i]; S += red[4 * NW + i];
        }
        float bg = __fsub_rn(1.0f, S);
        out[RGB_OFF + ray * 3 + 0] = R0 + bg;
        out[RGB_OFF + ray * 3 + 1] = R1 + bg;
        out[RGB_OFF + ray * 3 + 2] = R2 + bg;
        out[DEPTH_OFF + ray] = D;
    }
}

extern "C" void kernel_launch(void* const* d_in, const int* in_sizes, int n_in,
                              void* d_out, int out_size) {
    const float* rays_o = (const float*)d_in[0];
    const float* rays_d = (const float*)d_in[1];
    const float* grid   = (const float*)d_in[2];
    const float* atoms  = (const float*)d_in[3];
    float* out = (float*)d_out;

    // SMEM: R table (16*513 float4) + alpha(1536) + 3x srgb(1536) + scan(TPB) + red(80)
    const int smem_bytes = 16 * 513 * 16 + (1536 * 4 + TPB + 80) * 4;
    cudaFuncSetAttribute(render, cudaFuncAttributeMaxDynamicSharedMemorySize, smem_bytes);

    precompute_R<<<512, 256>>>(rays_d, atoms);
    render<<<128, TPB, smem_bytes>>>(rays_o, rays_d, grid, out);
}